// round 1
// baseline (speedup 1.0000x reference)
#include <cuda_runtime.h>

// SepKANLayer1D: per-token KAN edge-spline layer.
// x: (4, 8, 65536) f32, w: (4, 640, 65536) f32, out: (4, 8, 65536) f32.
// Per token t=(b,n): coef[i][o][k] = w[b, i*64+o*8+k, n] (512)
//                    uw[i][o]      = w[b, 512+i*8+o, n]  (64)
//                    rw[i][o]      = w[b, 576+i*8+o, n]  (64)
// basis(x_i): cubic B-spline, uniform knots t_j = -0.6 + 0.2*j, j=0..11 -> 8 bases.
// y[b,o,n] = sum_i uw[i][o]*sum_k basis_i[k]*coef[i][o][k] + silu(x_i)*rw[i][o]

#define IN_C   8
#define OUT_C  8
#define NB     8
#define NTOK   65536            // tokens per batch (N)
#define WSIZE  640

__global__ __launch_bounds__(256, 8)
void sepkan_kernel(const float* __restrict__ x,
                   const float* __restrict__ w,
                   float* __restrict__ out) {
    const int t = blockIdx.x * blockDim.x + threadIdx.x;   // 0 .. 262143
    const int b = t >> 16;
    const int n = t & (NTOK - 1);

    const float* xp = x + (size_t)b * IN_C * NTOK + n;
    const float* wp = w + (size_t)b * WSIZE * NTOK + n;

    float acc[OUT_C];
#pragma unroll
    for (int o = 0; o < OUT_C; ++o) acc[o] = 0.0f;

#pragma unroll 1   // keep code small; each iteration has ~80 independent loads (ample MLP)
    for (int i = 0; i < IN_C; ++i) {
        const float xi = __ldg(xp + i * NTOK);

        // ---- Cox-de Boor, degree 0..3, uniform knots t_j = -0.6 + 0.2*j ----
        float bs[11];
#pragma unroll
        for (int j = 0; j < 11; ++j) {
            const float t0 = -0.6f + 0.2f * (float)j;
            const float t1 = t0 + 0.2f;
            bs[j] = (xi >= t0 && xi < t1) ? 1.0f : 0.0f;
        }
#pragma unroll
        for (int p = 1; p <= 3; ++p) {
            const float inv = 1.0f / (0.2f * (float)p);
#pragma unroll
            for (int j = 0; j < 11; ++j) {
                if (j < 11 - p) {
                    const float tj   = -0.6f + 0.2f * (float)j;
                    const float tjp1 = -0.6f + 0.2f * (float)(j + p + 1);
                    // reads old bs[j], old bs[j+1] (ascending j: bs[j+1] not yet overwritten)
                    bs[j] = (xi - tj) * inv * bs[j] + (tjp1 - xi) * inv * bs[j + 1];
                }
            }
        }
        // bs[0..7] are the 8 cubic basis values.

        const float sx = xi / (1.0f + __expf(-xi));   // silu

        const float* wc = wp + (size_t)(i * OUT_C * NB) * NTOK;   // spline coefs for channel i
        const float* wu = wp + (size_t)(IN_C * OUT_C * NB + i * OUT_C) * NTOK;   // uw
        const float* wr = wp + (size_t)(IN_C * OUT_C * NB + IN_C * OUT_C + i * OUT_C) * NTOK; // rw

#pragma unroll
        for (int o = 0; o < OUT_C; ++o) {
            float sp = 0.0f;
#pragma unroll
            for (int k = 0; k < NB; ++k)
                sp = fmaf(bs[k], __ldg(wc + (size_t)(o * NB + k) * NTOK), sp);
            acc[o] = fmaf(__ldg(wu + (size_t)o * NTOK), sp, acc[o]);
            acc[o] = fmaf(sx, __ldg(wr + (size_t)o * NTOK), acc[o]);
        }
    }

    float* yp = out + (size_t)b * OUT_C * NTOK + n;
#pragma unroll
    for (int o = 0; o < OUT_C; ++o)
        yp[(size_t)o * NTOK] = acc[o];
}

extern "C" void kernel_launch(void* const* d_in, const int* in_sizes, int n_in,
                              void* d_out, int out_size) {
    const float* x = (const float*)d_in[0];   // (4, 8, 65536)
    const float* w = (const float*)d_in[1];   // (4, 640, 65536)
    float* out = (float*)d_out;               // (4, 8, 65536)

    const int total = 4 * NTOK;               // 262144 tokens
    const int threads = 256;
    const int blocks = total / threads;       // 1024
    sepkan_kernel<<<blocks, threads>>>(x, w, out);
}